// round 1
// baseline (speedup 1.0000x reference)
#include <cuda_runtime.h>

// Dense 3D convolution, stride 1, pad 1, K=3.
// x: [2, 32, 32, 96, 96] f32   (N, IC, D, H, W)
// w: [64, 32, 3, 3, 3]   f32   (OC, IC, KD, KH, KW)
// b: [64] f32
// y: [2, 64, 32, 96, 96] f32

#define NB 2
#define IC 32
#define OC 64
#define DD 32
#define HH 96
#define WW 96

#define W_T 32
#define H_T 4

#define IN_TILE (3 * (H_T + 2) * (W_T + 2))   // 612
#define W_TILE  (OC * 27)                     // 1728

__global__ __launch_bounds__(256, 2)
void conv3d_direct_kernel(const float* __restrict__ x,
                          const float* __restrict__ w,
                          const float* __restrict__ bias,
                          float* __restrict__ y)
{
    __shared__ float s_in[3][H_T + 2][W_T + 2];   // [kd][h][w] halo tile, one ic
    __shared__ float s_w[OC * 27];                // [oc][k] flat, one ic

    const int t  = threadIdx.x;
    const int tx = t & 31;          // output w lane
    const int ty = t >> 5;          // 0..7 -> oc group (warp-uniform)

    const int bx = blockIdx.x;      // 0..71 = (W/32=3) * (H/4=24)
    const int w0 = (bx % (WW / W_T)) * W_T;
    const int h0 = (bx / (WW / W_T)) * H_T;
    const int d  = blockIdx.y;
    const int n  = blockIdx.z;

    float acc[8][H_T];
    #pragma unroll
    for (int i = 0; i < 8; i++)
        #pragma unroll
        for (int j = 0; j < H_T; j++) acc[i][j] = 0.f;

    const float* xn = x + (size_t)n * IC * DD * HH * WW;

    for (int ic = 0; ic < IC; ++ic) {
        // ---- cooperative input halo load (612 f32, zero-padded) ----
        const float* xp = xn + (size_t)ic * DD * HH * WW;
        for (int i = t; i < IN_TILE; i += 256) {
            const int kd = i / ((H_T + 2) * (W_T + 2));
            const int r  = i % ((H_T + 2) * (W_T + 2));
            const int hh = r / (W_T + 2);
            const int ww = r % (W_T + 2);
            const int gd = d + kd - 1;
            const int gh = h0 + hh - 1;
            const int gw = w0 + ww - 1;
            float v = 0.f;
            if (gd >= 0 && gd < DD && gh >= 0 && gh < HH && gw >= 0 && gw < WW)
                v = xp[(gd * HH + gh) * WW + gw];
            (&s_in[0][0][0])[i] = v;
        }
        // ---- cooperative weight load (1728 f32, coalesced) ----
        // s_w[oc*27 + k] = w[oc*IC*27 + ic*27 + k]
        for (int i = t; i < W_TILE; i += 256) {
            const int oc = i / 27;
            const int k  = i - oc * 27;
            s_w[i] = w[oc * (IC * 27) + ic * 27 + k];
        }
        __syncthreads();

        // ---- compute: kd outer so the register input cache stays small ----
        #pragma unroll
        for (int kd = 0; kd < 3; kd++) {
            // register cache of this thread's input footprint for this kd:
            // rows h0-1 .. h0+4 (6), cols tx .. tx+2 (3)
            float rin[H_T + 2][3];
            #pragma unroll
            for (int hh = 0; hh < H_T + 2; hh++)
                #pragma unroll
                for (int kw = 0; kw < 3; kw++)
                    rin[hh][kw] = s_in[kd][hh][tx + kw];

            #pragma unroll
            for (int oi = 0; oi < 8; oi++) {
                const float* wp = &s_w[(ty * 8 + oi) * 27 + kd * 9];
                #pragma unroll
                for (int kh = 0; kh < 3; kh++) {
                    #pragma unroll
                    for (int kw = 0; kw < 3; kw++) {
                        const float wv = wp[kh * 3 + kw];   // warp-uniform LDS
                        #pragma unroll
                        for (int h = 0; h < H_T; h++)
                            acc[oi][h] += wv * rin[kh + h][kw];
                    }
                }
            }
        }
        __syncthreads();
    }

    // ---- epilogue ----
    #pragma unroll
    for (int oi = 0; oi < 8; oi++) {
        const int oc = ty * 8 + oi;
        const float b = bias[oc];
        float* yp = y + (((size_t)n * OC + oc) * DD + d) * (HH * WW);
        #pragma unroll
        for (int h = 0; h < H_T; h++)
            yp[(h0 + h) * WW + w0 + tx] = acc[oi][h] + b;
    }
}

extern "C" void kernel_launch(void* const* d_in, const int* in_sizes, int n_in,
                              void* d_out, int out_size)
{
    const float* x    = (const float*)d_in[0];
    const float* wgt  = (const float*)d_in[1];
    const float* bias = (const float*)d_in[2];
    float* y = (float*)d_out;

    dim3 grid((WW / W_T) * (HH / H_T), DD, NB);   // (72, 32, 2)
    conv3d_direct_kernel<<<grid, 256>>>(x, wgt, bias, y);
}